// round 2
// baseline (speedup 1.0000x reference)
#include <cuda_runtime.h>
#include <math.h>

#define T_DIM 500
#define B_DIM 32
#define U_DIM 100
#define I_DIM 1024
#define E_DIM 512
#define M_DIM 512
#define C_DIM 1024
#define O_DIM 512
#define G_DIM 4096            // 4*CELL
#define NUM_CLASS 5000
#define NB_ATT 100            // attention blocks (T/5)

// ---------------- scratch (device globals; no allocation allowed) ----------
__device__ float g_att_h[T_DIM * B_DIM * M_DIM];    // [t][b][m]   32.8 MB
__device__ float g_emb[U_DIM * E_DIM * B_DIM];      // [u][e][b]    6.6 MB
__device__ float g_gates[G_DIM * B_DIM];            // [j][b]
__device__ float g_c[C_DIM * B_DIM];                // [ci][b]
__device__ float g_h[C_DIM * B_DIM];                // [ci][b]
__device__ float g_p[O_DIM * B_DIM];                // [r][b]
__device__ float g_state[B_DIM * M_DIM];            // [b][m]
__device__ float g_ctx[I_DIM * B_DIM];              // [i][b]
__device__ float g_part[NB_ATT * B_DIM * I_DIM];    // [blk][b][i] 13.1 MB

__device__ __forceinline__ float fast_tanh(float x) {
    float y;
    asm("tanh.approx.f32 %0, %1;" : "=f"(y) : "f"(x));
    return y;
}
__device__ __forceinline__ float sigf(float x) { return 1.0f / (1.0f + expf(-x)); }

// ---------------- embedding (shift-right with SOS, mask invalid) -----------
__global__ void k_embed(const int* __restrict__ label, const float* __restrict__ embW) {
    int idx = blockIdx.x * 256 + threadIdx.x;           // over U*E*B = 1,638,400
    if (idx >= U_DIM * E_DIM * B_DIM) return;
    int b = idx & 31;
    int e = (idx >> 5) & (E_DIM - 1);
    int u = idx >> 14;                                  // E*B = 16384 = 2^14
    int lab = (u == 0) ? (NUM_CLASS - 2) : label[(u - 1) * B_DIM + b];
    float v = 0.0f;
    if (lab >= 0) v = embW[lab * E_DIM + e];
    g_emb[idx] = v;
}

// ---------------- att_h = data @ Wi2h^T  (16000 x 512 x 1024) --------------
// classic 64x64x16 tile, 256 threads, 4x4 per thread
__global__ void k_atth(const float* __restrict__ data, const float* __restrict__ Wi2h) {
    __shared__ float As[16][64];   // [k][n]
    __shared__ float Bs[16][64];   // [k][m]
    int n0 = blockIdx.x * 64;
    int m0 = blockIdx.y * 64;
    int tid = threadIdx.x;
    int tx = tid & 15, ty = tid >> 4;
    float acc[4][4];
#pragma unroll
    for (int i = 0; i < 4; i++)
#pragma unroll
        for (int j = 0; j < 4; j++) acc[i][j] = 0.0f;

    int kk = tid & 15, nn = tid >> 4;
    for (int k0 = 0; k0 < I_DIM; k0 += 16) {
#pragma unroll
        for (int r = 0; r < 4; r++)
            As[kk][nn + r * 16] = data[(n0 + nn + r * 16) * I_DIM + k0 + kk];
#pragma unroll
        for (int r = 0; r < 4; r++)
            Bs[kk][nn + r * 16] = Wi2h[(m0 + nn + r * 16) * I_DIM + k0 + kk];
        __syncthreads();
#pragma unroll
        for (int k = 0; k < 16; k++) {
            float a[4], bv[4];
#pragma unroll
            for (int i = 0; i < 4; i++) a[i] = As[k][ty * 4 + i];
#pragma unroll
            for (int j = 0; j < 4; j++) bv[j] = Bs[k][tx * 4 + j];
#pragma unroll
            for (int i = 0; i < 4; i++)
#pragma unroll
                for (int j = 0; j < 4; j++) acc[i][j] += a[i] * bv[j];
        }
        __syncthreads();
    }
#pragma unroll
    for (int i = 0; i < 4; i++)
#pragma unroll
        for (int j = 0; j < 4; j++)
            g_att_h[(n0 + ty * 4 + i) * M_DIM + m0 + tx * 4 + j] = acc[i][j];
}

// ---------------- zero initial state ---------------------------------------
__global__ void k_init() {
    int idx = blockIdx.x * 256 + threadIdx.x;   // 128 blocks -> 32768
    if (idx < C_DIM * B_DIM) g_c[idx] = 0.0f;
    if (idx < O_DIM * B_DIM) g_p[idx] = 0.0f;
    if (idx < I_DIM * B_DIM) g_ctx[idx] = 0.0f;
}

// ---------------- gates: [Wx|Wp] @ [emb;ctx;p] + b --------------------------
// grid 128 blocks, each 32 gate rows for all 32 batches; warp = 4 rows, lane = batch
__global__ void k_gates(const float* __restrict__ Wx, const float* __restrict__ Wp,
                        const float* __restrict__ bias, int u) {
    __shared__ float xs[128][32];
    int tid = threadIdx.x;
    int lane = tid & 31, w = tid >> 5;
    int j0 = blockIdx.x * 32 + w * 4;
    float acc0 = 0.f, acc1 = 0.f, acc2 = 0.f, acc3 = 0.f;
    const float* embu = g_emb + u * E_DIM * B_DIM;

    for (int kc = 0; kc < 16; kc++) {
        int k0 = kc * 128;
#pragma unroll
        for (int r = 0; r < 16; r++) {
            int idx = r * 256 + tid;
            int kkl = idx >> 5, bb = idx & 31;
            int k = k0 + kkl;
            float v;
            if (k < 512)        v = embu[k * 32 + bb];
            else if (k < 1536)  v = g_ctx[(k - 512) * 32 + bb];
            else                v = g_p[(k - 1536) * 32 + bb];
            xs[kkl][bb] = v;
        }
        __syncthreads();

        const float *w0, *w1, *w2, *w3;
        if (k0 < 1536) {
            w0 = Wx + (j0 + 0) * 1536 + k0;  w1 = Wx + (j0 + 1) * 1536 + k0;
            w2 = Wx + (j0 + 2) * 1536 + k0;  w3 = Wx + (j0 + 3) * 1536 + k0;
        } else {
            int kp = k0 - 1536;
            w0 = Wp + (j0 + 0) * 512 + kp;   w1 = Wp + (j0 + 1) * 512 + kp;
            w2 = Wp + (j0 + 2) * 512 + kp;   w3 = Wp + (j0 + 3) * 512 + kp;
        }
#pragma unroll 8
        for (int k = 0; k < 128; k += 4) {
            float4 a0 = *(const float4*)(w0 + k);
            float4 a1 = *(const float4*)(w1 + k);
            float4 a2 = *(const float4*)(w2 + k);
            float4 a3 = *(const float4*)(w3 + k);
            float x0 = xs[k + 0][lane], x1 = xs[k + 1][lane];
            float x2 = xs[k + 2][lane], x3 = xs[k + 3][lane];
            acc0 += a0.x * x0 + a0.y * x1 + a0.z * x2 + a0.w * x3;
            acc1 += a1.x * x0 + a1.y * x1 + a1.z * x2 + a1.w * x3;
            acc2 += a2.x * x0 + a2.y * x1 + a2.z * x2 + a2.w * x3;
            acc3 += a3.x * x0 + a3.y * x1 + a3.z * x2 + a3.w * x3;
        }
        __syncthreads();
    }
    g_gates[(j0 + 0) * 32 + lane] = acc0 + bias[j0 + 0];
    g_gates[(j0 + 1) * 32 + lane] = acc1 + bias[j0 + 1];
    g_gates[(j0 + 2) * 32 + lane] = acc2 + bias[j0 + 2];
    g_gates[(j0 + 3) * 32 + lane] = acc3 + bias[j0 + 3];
}

// ---------------- LSTM pointwise -------------------------------------------
__global__ void k_lstm() {
    int idx = blockIdx.x * 256 + threadIdx.x;   // 32768
    float ig = g_gates[idx];
    float fg = g_gates[32768 + idx];
    float gg = g_gates[65536 + idx];
    float og = g_gates[98304 + idx];
    float c = g_c[idx];
    c = sigf(fg) * c + sigf(ig) * tanhf(gg);
    c = fminf(fmaxf(c, -1.0f), 1.0f);
    g_c[idx] = c;
    g_h[idx] = sigf(og) * tanhf(c);
}

// ---------------- p = h @ Wproj^T, also write masked lstmp output ----------
__global__ void k_proj(const float* __restrict__ Wproj, const float* __restrict__ attm,
                       float* __restrict__ out, int u) {
    extern __shared__ float hs[];    // 1024*32 floats = 128 KB
    int tid = threadIdx.x;
#pragma unroll 8
    for (int r = 0; r < 128; r++) hs[r * 256 + tid] = g_h[r * 256 + tid];
    __syncthreads();
    int lane = tid & 31, w = tid >> 5;
    int r = blockIdx.x * 8 + w;      // 64 blocks -> 512 rows
    const float* wr = Wproj + r * 1024;
    float acc = 0.0f;
#pragma unroll 8
    for (int k = 0; k < 1024; k += 4) {
        float4 a = *(const float4*)(wr + k);
        acc += a.x * hs[(k + 0) * 32 + lane] + a.y * hs[(k + 1) * 32 + lane]
             + a.z * hs[(k + 2) * 32 + lane] + a.w * hs[(k + 3) * 32 + lane];
    }
    g_p[r * 32 + lane] = acc;
    out[u * (B_DIM * 1536) + lane * 1536 + r] = acc * attm[u * 32 + lane];
}

// ---------------- state = p @ Wp2s^T ----------------------------------------
__global__ void k_state(const float* __restrict__ Wp2s) {
    extern __shared__ float ps[];    // 512*32 floats = 64 KB
    int tid = threadIdx.x;
#pragma unroll 8
    for (int r = 0; r < 64; r++) ps[r * 256 + tid] = g_p[r * 256 + tid];
    __syncthreads();
    int lane = tid & 31, w = tid >> 5;
    int m = blockIdx.x * 8 + w;      // 64 blocks -> 512 rows
    const float* wr = Wp2s + m * 512;
    float acc = 0.0f;
#pragma unroll 8
    for (int k = 0; k < 512; k += 4) {
        float4 a = *(const float4*)(wr + k);
        acc += a.x * ps[(k + 0) * 32 + lane] + a.y * ps[(k + 1) * 32 + lane]
             + a.z * ps[(k + 2) * 32 + lane] + a.w * ps[(k + 3) * 32 + lane];
    }
    g_state[lane * 512 + m] = acc;
}

// ---------------- attention sweep over T: scalar + ctx partials -------------
// 100 blocks x 5 timesteps; ctx accumulator (128KB) + state (64KB) in smem
__global__ void k_attn(const float* __restrict__ data, const float* __restrict__ rnn_mask,
                       const float* __restrict__ wv) {
    extern __shared__ float sm[];
    float* acc = sm;               // 32768
    float* st  = sm + 32768;       // 16384
    float* wvs = sm + 49152;       // 512
    float* ssm = sm + 49664;       // 32
    int tid = threadIdx.x;
#pragma unroll 8
    for (int r = 0; r < 128; r++) acc[r * 256 + tid] = 0.0f;
#pragma unroll 8
    for (int r = 0; r < 64; r++) st[r * 256 + tid] = g_state[r * 256 + tid];
    for (int r = tid; r < 512; r += 256) wvs[r] = wv[r];
    __syncthreads();

    int lane = tid & 31, w = tid >> 5;
    int t0 = blockIdx.x * 5;
    for (int tt = 0; tt < 5; tt++) {
        int t = t0 + tt;
        // phase A: scalar[b] for the warp's 4 batches
        int b0 = w * 4;
#pragma unroll
        for (int bb = 0; bb < 4; bb++) {
            int b = b0 + bb;
            const float* ah  = g_att_h + (t * 32 + b) * 512;
            const float* stb = st + b * 512;
            float s = 0.0f;
#pragma unroll
            for (int it = 0; it < 16; it++) {
                int m = lane + it * 32;
                s += wvs[m] * fast_tanh(stb[m] + ah[m]);
            }
#pragma unroll
            for (int off = 16; off; off >>= 1) s += __shfl_xor_sync(0xffffffffu, s, off);
            if (lane == 0) {
                float biasv = (rnn_mask[t * 32 + b] - 1.0f) * 1e10f;
                ssm[b] = 1.0f / (1.0f + __expf(-(s + biasv)));
            }
        }
        __syncthreads();
        // phase B: ctx accumulation
        const float* dt = data + t * (B_DIM * I_DIM);
#pragma unroll 8
        for (int r = 0; r < 128; r++) {
            int idx = r * 256 + tid;
            acc[idx] += dt[idx] * ssm[idx >> 10];
        }
        __syncthreads();
    }
    float* part = g_part + blockIdx.x * (B_DIM * I_DIM);
#pragma unroll 8
    for (int r = 0; r < 128; r++) part[r * 256 + tid] = acc[r * 256 + tid];
}

// ---------------- reduce partials -> ctx (transposed) + masked ctx output ---
__global__ void k_reduce(const float* __restrict__ attm, float* __restrict__ out, int u) {
    int idx = blockIdx.x * 256 + threadIdx.x;    // 32768
    float s = 0.0f;
#pragma unroll 4
    for (int p = 0; p < NB_ATT; p++) s += g_part[p * 32768 + idx];
    int b = idx >> 10, i = idx & 1023;
    g_ctx[i * 32 + b] = s;
    out[u * (B_DIM * 1536) + b * 1536 + 512 + i] = s * attm[u * 32 + b];
}

// ---------------- launch ----------------------------------------------------
extern "C" void kernel_launch(void* const* d_in, const int* in_sizes, int n_in,
                              void* d_out, int out_size) {
    const float* data      = (const float*)d_in[0];
    const float* att_mask  = (const float*)d_in[1];
    const int*   att_label = (const int*)  d_in[2];
    const float* rnn_mask  = (const float*)d_in[3];
    const float* embW      = (const float*)d_in[4];
    const float* Wi2h      = (const float*)d_in[5];
    const float* Wp2s      = (const float*)d_in[6];
    const float* wv        = (const float*)d_in[7];
    const float* Wx        = (const float*)d_in[8];
    const float* Wp        = (const float*)d_in[9];
    const float* bias      = (const float*)d_in[10];
    const float* Wproj     = (const float*)d_in[11];
    float* out = (float*)d_out;

    cudaFuncSetAttribute(k_proj,  cudaFuncAttributeMaxDynamicSharedMemorySize, 131072);
    cudaFuncSetAttribute(k_state, cudaFuncAttributeMaxDynamicSharedMemorySize, 65536);
    cudaFuncSetAttribute(k_attn,  cudaFuncAttributeMaxDynamicSharedMemorySize, 198784);

    k_embed<<<6400, 256>>>(att_label, embW);
    dim3 gg(250, 8);
    k_atth<<<gg, 256>>>(data, Wi2h);
    k_init<<<128, 256>>>();

    for (int u = 0; u < U_DIM; u++) {
        k_gates<<<128, 256>>>(Wx, Wp, bias, u);
        k_lstm<<<128, 256>>>();
        k_proj<<<64, 256, 131072>>>(Wproj, att_mask, out, u);
        k_state<<<64, 256, 65536>>>(Wp2s);
        k_attn<<<NB_ATT, 256, 198784>>>(data, rnn_mask, wv);
        k_reduce<<<128, 256>>>(att_mask, out, u);
    }
}

// round 3
// speedup vs baseline: 4.3265x; 4.3265x over previous
#include <cuda_runtime.h>
#include <math.h>

#define T_DIM 500
#define B_DIM 32
#define U_DIM 100
#define I_DIM 1024
#define E_DIM 512
#define M_DIM 512
#define C_DIM 1024
#define O_DIM 512
#define G_DIM 4096
#define NUM_CLASS 5000

// ---------------- scratch ----------------------------------------------------
__device__ float g_att_h[T_DIM * B_DIM * M_DIM];     // [t*32+b][m]
__device__ float g_emb[U_DIM * E_DIM * B_DIM];       // [u][e][b]
__device__ float g_gpart[4 * G_DIM * B_DIM];         // [ky][j][b]
__device__ float g_ppart[8 * O_DIM * B_DIM];         // [ky][r][b]
__device__ float g_c[C_DIM * B_DIM];
__device__ float g_h[C_DIM * B_DIM];
__device__ float g_p[O_DIM * B_DIM];                 // [r][b]
__device__ float g_state[B_DIM * M_DIM];             // [b][m]
__device__ float g_ctx[I_DIM * B_DIM];               // [i][b]
__device__ float g_scalar[T_DIM * B_DIM];            // [t][b]
__device__ float g_cpart[5 * B_DIM * I_DIM];         // [chunk][b*1024+i]

__device__ __forceinline__ float fast_tanh(float x) {
    float y; asm("tanh.approx.f32 %0, %1;" : "=f"(y) : "f"(x)); return y;
}
__device__ __forceinline__ float sigf(float x) { return 1.0f / (1.0f + expf(-x)); }

// ---------------- embedding --------------------------------------------------
__global__ void k_embed(const int* __restrict__ label, const float* __restrict__ embW) {
    int idx = blockIdx.x * 256 + threadIdx.x;
    if (idx >= U_DIM * E_DIM * B_DIM) return;
    int b = idx & 31;
    int e = (idx >> 5) & (E_DIM - 1);
    int u = idx >> 14;
    int lab = (u == 0) ? (NUM_CLASS - 2) : label[(u - 1) * B_DIM + b];
    float v = 0.0f;
    if (lab >= 0) v = embW[lab * E_DIM + e];
    g_emb[idx] = v;
}

// ---------------- att_h = data @ Wi2h^T (16000 x 512 x 1024) -----------------
__global__ void k_atth(const float* __restrict__ data, const float* __restrict__ Wi2h) {
    __shared__ float As[16][64];
    __shared__ float Bs[16][64];
    int n0 = blockIdx.x * 64, m0 = blockIdx.y * 64;
    int tid = threadIdx.x;
    int tx = tid & 15, ty = tid >> 4;
    float acc[4][4];
#pragma unroll
    for (int i = 0; i < 4; i++)
#pragma unroll
        for (int j = 0; j < 4; j++) acc[i][j] = 0.0f;
    int kk = tid & 15, nn = tid >> 4;
    for (int k0 = 0; k0 < I_DIM; k0 += 16) {
#pragma unroll
        for (int r = 0; r < 4; r++)
            As[kk][nn + r * 16] = __ldcs(&data[(n0 + nn + r * 16) * I_DIM + k0 + kk]);
#pragma unroll
        for (int r = 0; r < 4; r++)
            Bs[kk][nn + r * 16] = Wi2h[(m0 + nn + r * 16) * I_DIM + k0 + kk];
        __syncthreads();
#pragma unroll
        for (int k = 0; k < 16; k++) {
            float4 a = *(const float4*)&As[k][ty * 4];
            float4 bv = *(const float4*)&Bs[k][tx * 4];
            acc[0][0] += a.x * bv.x; acc[0][1] += a.x * bv.y; acc[0][2] += a.x * bv.z; acc[0][3] += a.x * bv.w;
            acc[1][0] += a.y * bv.x; acc[1][1] += a.y * bv.y; acc[1][2] += a.y * bv.z; acc[1][3] += a.y * bv.w;
            acc[2][0] += a.z * bv.x; acc[2][1] += a.z * bv.y; acc[2][2] += a.z * bv.z; acc[2][3] += a.z * bv.w;
            acc[3][0] += a.w * bv.x; acc[3][1] += a.w * bv.y; acc[3][2] += a.w * bv.z; acc[3][3] += a.w * bv.w;
        }
        __syncthreads();
    }
#pragma unroll
    for (int i = 0; i < 4; i++)
#pragma unroll
        for (int j = 0; j < 4; j++)
            g_att_h[(n0 + ty * 4 + i) * M_DIM + m0 + tx * 4 + j] = acc[i][j];
}

__global__ void k_init() {
    int idx = blockIdx.x * 256 + threadIdx.x;
    if (idx < C_DIM * B_DIM) g_c[idx] = 0.0f;
    if (idx < O_DIM * B_DIM) g_p[idx] = 0.0f;
    if (idx < I_DIM * B_DIM) g_ctx[idx] = 0.0f;
}

// ---------------- gates partial GEMM: smem-staged, 64 rows x 512 k per block --
// grid (64, 4): x = rowblock (64 rows), y = k-split. warp = 8 rows, lane = batch.
__global__ void k_gates(const float* __restrict__ Wx, const float* __restrict__ Wp, int u) {
    __shared__ float Wsm[64 * 64];       // [row][k]
    __shared__ float xsm[64 * 33];       // [k][b] padded
    int tid = threadIdx.x;
    int lane = tid & 31, w = tid >> 5;
    int ky = blockIdx.y;
    int row0 = blockIdx.x * 64;

    const float* xsrc;
    if (ky == 0)      xsrc = g_emb + u * (E_DIM * B_DIM);
    else if (ky == 1) xsrc = g_ctx;
    else if (ky == 2) xsrc = g_ctx + 512 * 32;
    else              xsrc = g_p;
    const float* wsrc; int wstride;
    if (ky < 3) { wsrc = Wx + ky * 512; wstride = 1536; }
    else        { wsrc = Wp;            wstride = 512;  }

    float acc[8];
#pragma unroll
    for (int r = 0; r < 8; r++) acc[r] = 0.0f;

    float4 wr[4], xr[2];
    // prefetch sub 0
    {
        int k0 = 0;
#pragma unroll
        for (int q = 0; q < 4; q++) {
            int idx = q * 256 + tid; int r = idx >> 4, c = (idx & 15) * 4;
            wr[q] = *(const float4*)&wsrc[(row0 + r) * wstride + k0 + c];
        }
#pragma unroll
        for (int q = 0; q < 2; q++) {
            int idx = q * 256 + tid; int k = idx >> 3, b = (idx & 7) * 4;
            xr[q] = *(const float4*)&xsrc[(k0 + k) * 32 + b];
        }
    }
    for (int sub = 0; sub < 8; sub++) {
        __syncthreads();
#pragma unroll
        for (int q = 0; q < 4; q++) {
            int idx = q * 256 + tid; int r = idx >> 4, c = (idx & 15) * 4;
            *(float4*)&Wsm[r * 64 + c] = wr[q];
        }
#pragma unroll
        for (int q = 0; q < 2; q++) {
            int idx = q * 256 + tid; int k = idx >> 3, b = (idx & 7) * 4;
            float4 v = xr[q]; int base = k * 33 + b;
            xsm[base] = v.x; xsm[base + 1] = v.y; xsm[base + 2] = v.z; xsm[base + 3] = v.w;
        }
        __syncthreads();
        if (sub < 7) {
            int k0 = (sub + 1) * 64;
#pragma unroll
            for (int q = 0; q < 4; q++) {
                int idx = q * 256 + tid; int r = idx >> 4, c = (idx & 15) * 4;
                wr[q] = *(const float4*)&wsrc[(row0 + r) * wstride + k0 + c];
            }
#pragma unroll
            for (int q = 0; q < 2; q++) {
                int idx = q * 256 + tid; int k = idx >> 3, b = (idx & 7) * 4;
                xr[q] = *(const float4*)&xsrc[(k0 + k) * 32 + b];
            }
        }
#pragma unroll 4
        for (int kk = 0; kk < 64; kk += 4) {
            float x0 = xsm[kk * 33 + lane];
            float x1 = xsm[(kk + 1) * 33 + lane];
            float x2 = xsm[(kk + 2) * 33 + lane];
            float x3 = xsm[(kk + 3) * 33 + lane];
#pragma unroll
            for (int r = 0; r < 8; r++) {
                float4 wv = *(const float4*)&Wsm[(w * 8 + r) * 64 + kk];
                acc[r] += wv.x * x0 + wv.y * x1 + wv.z * x2 + wv.w * x3;
            }
        }
    }
#pragma unroll
    for (int r = 0; r < 8; r++) {
        int j = row0 + w * 8 + r;
        g_gpart[ky * (G_DIM * 32) + j * 32 + lane] = acc[r];
    }
}

// ---------------- LSTM pointwise (+ gate partial reduction) ------------------
__global__ void k_lstm(const float* __restrict__ bias) {
    int idx = blockIdx.x * 256 + threadIdx.x;  // ci*32+b
    int ci = idx >> 5, b = idx & 31;
    float gt[4];
#pragma unroll
    for (int gi = 0; gi < 4; gi++) {
        int j = gi * 1024 + ci;
        float s = bias[j];
#pragma unroll
        for (int ky = 0; ky < 4; ky++) s += g_gpart[ky * (G_DIM * 32) + j * 32 + b];
        gt[gi] = s;
    }
    float c = g_c[idx];
    c = sigf(gt[1]) * c + sigf(gt[0]) * tanhf(gt[2]);
    c = fminf(fmaxf(c, -1.0f), 1.0f);
    g_c[idx] = c;
    g_h[idx] = sigf(gt[3]) * tanhf(c);
}

// ---------------- proj partial GEMM: 64 rows x 128 k per block ---------------
// grid (8, 8): rowblock 64, ksplit 8 (chunk 128 = 2 subs of 64)
__global__ void k_proj(const float* __restrict__ Wproj) {
    __shared__ float Wsm[64 * 64];
    __shared__ float xsm[64 * 33];
    int tid = threadIdx.x;
    int lane = tid & 31, w = tid >> 5;
    int ky = blockIdx.y;
    int row0 = blockIdx.x * 64;
    const float* wsrc = Wproj + ky * 128;
    const float* xsrc = g_h + ky * 128 * 32;

    float acc[8];
#pragma unroll
    for (int r = 0; r < 8; r++) acc[r] = 0.0f;
    float4 wr[4], xr[2];
    {
#pragma unroll
        for (int q = 0; q < 4; q++) {
            int idx = q * 256 + tid; int r = idx >> 4, c = (idx & 15) * 4;
            wr[q] = *(const float4*)&wsrc[(row0 + r) * 1024 + c];
        }
#pragma unroll
        for (int q = 0; q < 2; q++) {
            int idx = q * 256 + tid; int k = idx >> 3, b = (idx & 7) * 4;
            xr[q] = *(const float4*)&xsrc[k * 32 + b];
        }
    }
    for (int sub = 0; sub < 2; sub++) {
        __syncthreads();
#pragma unroll
        for (int q = 0; q < 4; q++) {
            int idx = q * 256 + tid; int r = idx >> 4, c = (idx & 15) * 4;
            *(float4*)&Wsm[r * 64 + c] = wr[q];
        }
#pragma unroll
        for (int q = 0; q < 2; q++) {
            int idx = q * 256 + tid; int k = idx >> 3, b = (idx & 7) * 4;
            float4 v = xr[q]; int base = k * 33 + b;
            xsm[base] = v.x; xsm[base + 1] = v.y; xsm[base + 2] = v.z; xsm[base + 3] = v.w;
        }
        __syncthreads();
        if (sub < 1) {
            int k0 = 64;
#pragma unroll
            for (int q = 0; q < 4; q++) {
                int idx = q * 256 + tid; int r = idx >> 4, c = (idx & 15) * 4;
                wr[q] = *(const float4*)&wsrc[(row0 + r) * 1024 + k0 + c];
            }
#pragma unroll
            for (int q = 0; q < 2; q++) {
                int idx = q * 256 + tid; int k = idx >> 3, b = (idx & 7) * 4;
                xr[q] = *(const float4*)&xsrc[(k0 + k) * 32 + b];
            }
        }
#pragma unroll 4
        for (int kk = 0; kk < 64; kk += 4) {
            float x0 = xsm[kk * 33 + lane];
            float x1 = xsm[(kk + 1) * 33 + lane];
            float x2 = xsm[(kk + 2) * 33 + lane];
            float x3 = xsm[(kk + 3) * 33 + lane];
#pragma unroll
            for (int r = 0; r < 8; r++) {
                float4 wv = *(const float4*)&Wsm[(w * 8 + r) * 64 + kk];
                acc[r] += wv.x * x0 + wv.y * x1 + wv.z * x2 + wv.w * x3;
            }
        }
    }
#pragma unroll
    for (int r = 0; r < 8; r++) {
        int j = row0 + w * 8 + r;
        g_ppart[ky * (O_DIM * 32) + j * 32 + lane] = acc[r];
    }
}

// ---------------- reduce proj partials -> p, write masked lstmp output -------
__global__ void k_pfix(const float* __restrict__ attm, float* __restrict__ out, int u) {
    int idx = blockIdx.x * 256 + threadIdx.x;   // 16384: r*32+b
    float s = 0.0f;
#pragma unroll
    for (int ky = 0; ky < 8; ky++) s += g_ppart[ky * (O_DIM * 32) + idx];
    g_p[idx] = s;
    int r = idx >> 5, b = idx & 31;
    out[u * (B_DIM * 1536) + b * 1536 + r] = s * attm[u * 32 + b];
}

// ---------------- state = Wp2s @ p : 8 blocks, 64 rows each, K=512 -----------
__global__ void k_state(const float* __restrict__ Wp2s) {
    __shared__ float Wsm[64 * 64];
    __shared__ float xsm[64 * 33];
    int tid = threadIdx.x;
    int lane = tid & 31, w = tid >> 5;
    int row0 = blockIdx.x * 64;

    float acc[8];
#pragma unroll
    for (int r = 0; r < 8; r++) acc[r] = 0.0f;
    float4 wr[4], xr[2];
    {
#pragma unroll
        for (int q = 0; q < 4; q++) {
            int idx = q * 256 + tid; int r = idx >> 4, c = (idx & 15) * 4;
            wr[q] = *(const float4*)&Wp2s[(row0 + r) * 512 + c];
        }
#pragma unroll
        for (int q = 0; q < 2; q++) {
            int idx = q * 256 + tid; int k = idx >> 3, b = (idx & 7) * 4;
            xr[q] = *(const float4*)&g_p[k * 32 + b];
        }
    }
    for (int sub = 0; sub < 8; sub++) {
        __syncthreads();
#pragma unroll
        for (int q = 0; q < 4; q++) {
            int idx = q * 256 + tid; int r = idx >> 4, c = (idx & 15) * 4;
            *(float4*)&Wsm[r * 64 + c] = wr[q];
        }
#pragma unroll
        for (int q = 0; q < 2; q++) {
            int idx = q * 256 + tid; int k = idx >> 3, b = (idx & 7) * 4;
            float4 v = xr[q]; int base = k * 33 + b;
            xsm[base] = v.x; xsm[base + 1] = v.y; xsm[base + 2] = v.z; xsm[base + 3] = v.w;
        }
        __syncthreads();
        if (sub < 7) {
            int k0 = (sub + 1) * 64;
#pragma unroll
            for (int q = 0; q < 4; q++) {
                int idx = q * 256 + tid; int r = idx >> 4, c = (idx & 15) * 4;
                wr[q] = *(const float4*)&Wp2s[(row0 + r) * 512 + k0 + c];
            }
#pragma unroll
            for (int q = 0; q < 2; q++) {
                int idx = q * 256 + tid; int k = idx >> 3, b = (idx & 7) * 4;
                xr[q] = *(const float4*)&g_p[(k0 + k) * 32 + b];
            }
        }
#pragma unroll 4
        for (int kk = 0; kk < 64; kk += 4) {
            float x0 = xsm[kk * 33 + lane];
            float x1 = xsm[(kk + 1) * 33 + lane];
            float x2 = xsm[(kk + 2) * 33 + lane];
            float x3 = xsm[(kk + 3) * 33 + lane];
#pragma unroll
            for (int r = 0; r < 8; r++) {
                float4 wv = *(const float4*)&Wsm[(w * 8 + r) * 64 + kk];
                acc[r] += wv.x * x0 + wv.y * x1 + wv.z * x2 + wv.w * x3;
            }
        }
    }
#pragma unroll
    for (int r = 0; r < 8; r++) {
        int m = row0 + w * 8 + r;
        g_state[lane * 512 + m] = acc[r];   // [b][m]
    }
}

// ---------------- attention scalars: one block per t --------------------------
__global__ void k_scalar(const float* __restrict__ rnn_mask, const float* __restrict__ wv) {
    __shared__ float wvs[512];
    int tid = threadIdx.x;
    int lane = tid & 31, w = tid >> 5;   // w in 0..15
    if (tid < 512) wvs[tid] = wv[tid];
    __syncthreads();
    int t = blockIdx.x;
#pragma unroll
    for (int rep = 0; rep < 2; rep++) {
        int b = w + rep * 16;
        const float* ah = g_att_h + (t * 32 + b) * 512;
        const float* st = g_state + b * 512;
        float s = 0.0f;
#pragma unroll
        for (int it = 0; it < 16; it++) {
            int m = lane + it * 32;
            s += wvs[m] * fast_tanh(st[m] + ah[m]);
        }
#pragma unroll
        for (int off = 16; off; off >>= 1) s += __shfl_xor_sync(0xffffffffu, s, off);
        if (lane == 0) {
            float bv = (rnn_mask[t * 32 + b] - 1.0f) * 1e10f;
            g_scalar[t * 32 + b] = 1.0f / (1.0f + __expf(-(s + bv)));
        }
    }
}

// ---------------- ctx partials: grid (128, 5) ---------------------------------
__global__ void k_ctx(const float* __restrict__ data) {
    __shared__ float ssm[100];
    int tid = threadIdx.x;
    int t0 = blockIdx.y * 100;
    int idx = blockIdx.x * 256 + tid;          // b*1024 + i
    int b = blockIdx.x >> 2;
    if (tid < 100) ssm[tid] = g_scalar[(t0 + tid) * 32 + b];
    __syncthreads();
    float a0 = 0.0f, a1 = 0.0f;
#pragma unroll 2
    for (int tt = 0; tt < 100; tt += 4) {
        a0 += __ldcs(&data[(t0 + tt + 0) * 32768 + idx]) * ssm[tt + 0];
        a1 += __ldcs(&data[(t0 + tt + 1) * 32768 + idx]) * ssm[tt + 1];
        a0 += __ldcs(&data[(t0 + tt + 2) * 32768 + idx]) * ssm[tt + 2];
        a1 += __ldcs(&data[(t0 + tt + 3) * 32768 + idx]) * ssm[tt + 3];
    }
    g_cpart[blockIdx.y * 32768 + idx] = a0 + a1;
}

// ---------------- reduce ctx partials -> ctx[k][b] + masked ctx output --------
__global__ void k_reduce(const float* __restrict__ attm, float* __restrict__ out, int u) {
    int idx = blockIdx.x * 256 + threadIdx.x;   // b*1024 + i
    float s = 0.0f;
#pragma unroll
    for (int p = 0; p < 5; p++) s += g_cpart[p * 32768 + idx];
    int b = idx >> 10, i = idx & 1023;
    g_ctx[i * 32 + b] = s;
    out[u * (B_DIM * 1536) + b * 1536 + 512 + i] = s * attm[u * 32 + b];
}

// ---------------- launch -------------------------------------------------------
extern "C" void kernel_launch(void* const* d_in, const int* in_sizes, int n_in,
                              void* d_out, int out_size) {
    const float* data      = (const float*)d_in[0];
    const float* att_mask  = (const float*)d_in[1];
    const int*   att_label = (const int*)  d_in[2];
    const float* rnn_mask  = (const float*)d_in[3];
    const float* embW      = (const float*)d_in[4];
    const float* Wi2h      = (const float*)d_in[5];
    const float* Wp2s      = (const float*)d_in[6];
    const float* wv        = (const float*)d_in[7];
    const float* Wx        = (const float*)d_in[8];
    const float* Wp        = (const float*)d_in[9];
    const float* bias      = (const float*)d_in[10];
    const float* Wproj     = (const float*)d_in[11];
    float* out = (float*)d_out;

    k_embed<<<6400, 256>>>(att_label, embW);
    dim3 gg(250, 8);
    k_atth<<<gg, 256>>>(data, Wi2h);
    k_init<<<128, 256>>>();

    for (int u = 0; u < U_DIM; u++) {
        k_gates<<<dim3(64, 4), 256>>>(Wx, Wp, u);
        k_lstm<<<128, 256>>>(bias);
        k_proj<<<dim3(8, 8), 256>>>(Wproj);
        k_pfix<<<64, 256>>>(att_mask, out, u);
        k_state<<<8, 256>>>(Wp2s);
        k_scalar<<<500, 512>>>(rnn_mask, wv);
        k_ctx<<<dim3(128, 5), 256>>>(data);
        k_reduce<<<128, 256>>>(att_mask, out, u);
    }
}